// round 4
// baseline (speedup 1.0000x reference)
#include <cuda_runtime.h>
#include <cstdint>

// BKT 2-state HMM forward-backward, 64-way time-segmented matrix scan.
// corr: (B,T) int32 ; dynamics_logits: (B,3) f32 ; obs_logits: (B,T,2) f32
// out: (3,B,T,2) f32 = [output_logprobs, state_posteriors, smoothed]

#define BN   8192
#define TT   1024
#define SEG  64
#define L    16
#define LN2F 0.69314718055994531f

__device__ float2 g_py[(size_t)TT * BN]; // t-major: (py0 [sign=y], py1)
__device__ float4 g_P4[SEG * BN];        // segment 2x2 products
__device__ int    g_E [SEG * BN];        // segment log2 scale
__device__ float4 g_ab[SEG * BN];        // (a0,a1,C,-) normalized alpha at segment start
__device__ float2 g_bb[SEG * BN];        // (b0,b1) beta at segment end

__device__ __forceinline__ void trans_from_dyn(const float* __restrict__ dyn, int row,
                                               float& t00, float& t10, float& t01, float& t11)
{
    float d0 = dyn[row * 3 + 0];
    float d1 = dyn[row * 3 + 1];
    float e0 = __expf(d0), e1 = __expf(d1);
    float r0 = __frcp_rn(1.f + e0);
    float r1 = __frcp_rn(1.f + e1);
    t00 = r0;      t10 = e0 * r0;   // src=0 column (sums to 1)
    t01 = e1 * r1; t11 = r1;        // src=1 column (sums to 1)
}

// ---------------- K1: emissions + per-segment 2x2 matrix products ----------------
__global__ __launch_bounds__(256)
void k1_products(const int* __restrict__ corr,
                 const float* __restrict__ dyn,
                 const float* __restrict__ obs)
{
    const int g   = blockIdx.x * 256 + threadIdx.x;   // g = seg*BN + row
    const int row = g & (BN - 1);
    const int seg = g >> 13;

    float t00, t10, t01, t11;
    trans_from_dyn(dyn, row, t00, t10, t01, t11);

    float o[2 * L];
    const float4* op = (const float4*)(obs + ((size_t)row * TT + seg * L) * 2);
#pragma unroll
    for (int i = 0; i < 8; i++) {
        float4 v = op[i];
        o[4 * i + 0] = v.x; o[4 * i + 1] = v.y;
        o[4 * i + 2] = v.z; o[4 * i + 3] = v.w;
    }
    int yb[L];
    const int4* cp = (const int4*)(corr + (size_t)row * TT + seg * L);
#pragma unroll
    for (int i = 0; i < 4; i++) {
        int4 v = cp[i];
        yb[4 * i + 0] = v.x; yb[4 * i + 1] = v.y;
        yb[4 * i + 2] = v.z; yb[4 * i + 3] = v.w;
    }

    float A00 = 1.f, A01 = 0.f, A10 = 0.f, A11 = 1.f;
    int E = 0;
#pragma unroll
    for (int j = 0; j < L; j++) {
        float e0 = __expf(o[2 * j]), e1 = __expf(o[2 * j + 1]);
        float r0 = __frcp_rn(1.f + e0);
        float r1 = __frcp_rn(1.f + e1);
        float py0 = yb[j] ? e0 * r0 : r0;
        float py1 = yb[j] ? r1 : e1 * r1;

        int t = seg * L + j;
        g_py[(size_t)t * BN + row] =
            make_float2(__int_as_float(__float_as_int(py0) | (yb[j] << 31)), py1);

        float m00 = t00 * py0, m01 = t01 * py1;
        float m10 = t10 * py0, m11 = t11 * py1;
        float n00 = m00 * A00 + m01 * A10;
        float n01 = m00 * A01 + m01 * A11;
        float n10 = m10 * A00 + m11 * A10;
        float n11 = m10 * A01 + m11 * A11;
        float s = (n00 + n01) + (n10 + n11);
        int eb = (__float_as_int(s) >> 23) & 0xFF;
        float sc = __int_as_float((254 - eb) << 23);
        A00 = n00 * sc; A01 = n01 * sc; A10 = n10 * sc; A11 = n11 * sc;
        E += eb - 127;
    }
    g_P4[g] = make_float4(A00, A01, A10, A11);
    g_E[g]  = E;
}

// ---------------- K2: boundary scan over segments ----------------
__global__ __launch_bounds__(256)
void k2_scan(const float* __restrict__ dyn)
{
    const int row = blockIdx.x * 256 + threadIdx.x;

    float d2 = dyn[row * 3 + 2];
    float ed2 = __expf(d2);
    float ri2 = __frcp_rn(1.f + ed2);
    float a0 = ri2, a1 = ed2 * ri2;
    int Ea = 0;

#pragma unroll 8
    for (int k = 0; k < SEG; k++) {
        int gi = k * BN + row;
        float s  = a0 + a1;
        float rs = __frcp_rn(s);
        float C  = (float)Ea * LN2F + __logf(s);
        g_ab[gi] = make_float4(a0 * rs, a1 * rs, C, 0.f);

        float4 P = g_P4[gi];
        int Ek   = g_E[gi];
        float na0 = P.x * a0 + P.y * a1;
        float na1 = P.z * a0 + P.w * a1;
        float ss = na0 + na1;
        int eb = (__float_as_int(ss) >> 23) & 0xFF;
        float sc = __int_as_float((254 - eb) << 23);
        a0 = na0 * sc; a1 = na1 * sc;
        Ea += Ek + (eb - 127);
    }

    float b0 = 1.f, b1 = 1.f;
#pragma unroll 8
    for (int k = SEG - 1; k >= 1; k--) {
        int gi = k * BN + row;
        g_bb[gi] = make_float2(b0, b1);
        float4 P = g_P4[gi];
        float nb0 = P.x * b0 + P.z * b1;   // P^T * b
        float nb1 = P.y * b0 + P.w * b1;
        float ss = nb0 + nb1;
        int eb = (__float_as_int(ss) >> 23) & 0xFF;
        float sc = __int_as_float((254 - eb) << 23);
        b0 = nb0 * sc; b1 = nb1 * sc;
    }
    g_bb[row] = make_float2(b0, b1);
}

// ---------------- K3: per-segment outputs (normalized filter, no sigmoids) ----------------
__global__ __launch_bounds__(64, 12)
void k3_outputs(const float* __restrict__ dyn, float* __restrict__ out)
{
    __shared__ float sA[64 * 33];
    __shared__ float sB[64 * 33];

    const int tid  = threadIdx.x;
    const int row0 = blockIdx.x * 64;
    const int row  = row0 + tid;
    const int seg  = blockIdx.y;

    float t00, t10, t01, t11;
    trans_from_dyn(dyn, row, t00, t10, t01, t11);

    float* outPred = out;
    float* outPost = out + (size_t)BN * TT * 2;
    float* outSm   = out + (size_t)2 * BN * TT * 2;

    // batch-load emissions (t-major, coalesced; L2-hot right after K1)
    float2 py2[L];
#pragma unroll
    for (int j = 0; j < L; j++)
        py2[j] = g_py[(size_t)(seg * L + j) * BN + row];

    const int gi = seg * BN + row;
    float4 ab = g_ab[gi];
    float a0 = ab.x, a1 = ab.y, C = ab.z;

    float f0s[L];

    // ---- forward: pred + post + f0 ----
#pragma unroll
    for (int j = 0; j < L; j++) {
        int y = __float_as_int(py2[j].x) >> 31;   // all-ones if y=1
        float py0 = fabsf(py2[j].x);
        float py1 = py2[j].y;

        float jj0 = a0 * py0;
        float jj1 = a1 * py1;
        float js  = jj0 + jj1;               // predictive prob of observed symbol
        float ljs = __logf(js);
        float lns = __logf(1.f - js);        // predictive probs sum to 1 (a normalized)
        float lp0 = y ? lns : ljs;
        float lp1 = y ? ljs : lns;
        float post0 = __logf(jj0) + C;
        float post1 = __logf(jj1) + C;

        float f = jj0 * __frcp_rn(js);
        f0s[j] = f;
        float fc = 1.f - f;
        a0 = t00 * f + t01 * fc;             // stays normalized (columns of T sum to 1)
        a1 = t10 * f + t11 * fc;
        C += ljs;

        sA[tid * 33 + 2 * j]     = lp0;
        sA[tid * 33 + 2 * j + 1] = lp1;
        sB[tid * 33 + 2 * j]     = post0;
        sB[tid * 33 + 2 * j + 1] = post1;
    }
    __syncthreads();
#pragma unroll
    for (int i = 0; i < 32; i++) {
        int idx = i * 64 + tid;
        int r = idx >> 5, p = idx & 31;
        size_t g = (size_t)(row0 + r) * (TT * 2) + (size_t)seg * (L * 2) + p;
        outPred[g] = sA[r * 33 + p];
        outPost[g] = sB[r * 33 + p];
    }
    __syncthreads();

    // ---- backward: smoothed ----
    float2 bb = g_bb[gi];
    float b0 = bb.x, b1 = bb.y;

#pragma unroll
    for (int j = L - 1; j >= 0; j--) {
        float f = f0s[j];
        float g0 = f * b0;
        float g1 = (1.f - f) * b1;
        float rs = __frcp_rn(g0 + g1);
        sA[tid * 33 + 2 * j]     = __logf(g0 * rs);
        sA[tid * 33 + 2 * j + 1] = __logf(g1 * rs);

        float py0 = fabsf(py2[j].x);
        float py1 = py2[j].y;
        float u0 = py0 * b0;
        float u1 = py1 * b1;
        float nb0 = t00 * u0 + t10 * u1;
        float nb1 = t01 * u0 + t11 * u1;
        float ss = nb0 + nb1;
        int eb = (__float_as_int(ss) >> 23) & 0xFF;
        float sc = __int_as_float((254 - eb) << 23);
        b0 = nb0 * sc; b1 = nb1 * sc;
    }
    __syncthreads();
#pragma unroll
    for (int i = 0; i < 32; i++) {
        int idx = i * 64 + tid;
        int r = idx >> 5, p = idx & 31;
        size_t g = (size_t)(row0 + r) * (TT * 2) + (size_t)seg * (L * 2) + p;
        outSm[g] = sA[r * 33 + p];
    }
}

extern "C" void kernel_launch(void* const* d_in, const int* in_sizes, int n_in,
                              void* d_out, int out_size)
{
    const int*   corr = (const int*)d_in[0];
    const float* dyn  = (const float*)d_in[1];
    const float* obs  = (const float*)d_in[2];
    float* out = (float*)d_out;

    k1_products<<<(BN * SEG) / 256, 256>>>(corr, dyn, obs);
    k2_scan<<<BN / 256, 256>>>(dyn);
    dim3 g3(BN / 64, SEG);
    k3_outputs<<<g3, 64>>>(dyn, out);
}

// round 5
// speedup vs baseline: 1.0930x; 1.0930x over previous
#include <cuda_runtime.h>
#include <cstdint>

// BKT 2-state HMM forward-backward, 128-way time-segmented matrix scan.
// corr: (B,T) int32 ; dynamics_logits: (B,3) f32 ; obs_logits: (B,T,2) f32
// out: (3,B,T,2) f32 = [output_logprobs, state_posteriors, smoothed]

#define BN   8192
#define TT   1024
#define SEG  128
#define L    8
#define LN2F 0.69314718055994531f

__device__ float4 g_P4[SEG * BN];   // segment 2x2 products (normalized)
__device__ int    g_E [SEG * BN];   // segment log2 scale
__device__ float4 g_ab[SEG * BN];   // (a0,a1,C,-) normalized alpha at segment start
__device__ float2 g_bb[SEG * BN];   // (b0,b1) beta at segment end

__device__ __forceinline__ void trans_from_dyn(const float* __restrict__ dyn, int row,
                                               float& t00, float& t10, float& t01, float& t11)
{
    float d0 = dyn[row * 3 + 0];
    float d1 = dyn[row * 3 + 1];
    float e0 = __expf(d0), e1 = __expf(d1);
    float r0 = __frcp_rn(1.f + e0);
    float r1 = __frcp_rn(1.f + e1);
    t00 = r0;      t10 = e0 * r0;   // src=0 column (sums to 1)
    t01 = e1 * r1; t11 = r1;        // src=1 column (sums to 1)
}

// ---------------- K1: per-segment 2x2 matrix products ----------------
__global__ __launch_bounds__(256)
void k1_products(const int* __restrict__ corr,
                 const float* __restrict__ dyn,
                 const float* __restrict__ obs)
{
    const int g   = blockIdx.x * 256 + threadIdx.x;   // g = seg*BN + row
    const int row = g & (BN - 1);
    const int seg = g >> 13;

    float t00, t10, t01, t11;
    trans_from_dyn(dyn, row, t00, t10, t01, t11);

    float o[2 * L];
    const float4* op = (const float4*)(obs + ((size_t)row * TT + seg * L) * 2);
#pragma unroll
    for (int i = 0; i < 4; i++) {
        float4 v = op[i];
        o[4 * i + 0] = v.x; o[4 * i + 1] = v.y;
        o[4 * i + 2] = v.z; o[4 * i + 3] = v.w;
    }
    int yb[L];
    const int4* cp = (const int4*)(corr + (size_t)row * TT + seg * L);
#pragma unroll
    for (int i = 0; i < 2; i++) {
        int4 v = cp[i];
        yb[4 * i + 0] = v.x; yb[4 * i + 1] = v.y;
        yb[4 * i + 2] = v.z; yb[4 * i + 3] = v.w;
    }

    float A00 = 1.f, A01 = 0.f, A10 = 0.f, A11 = 1.f;
#pragma unroll
    for (int j = 0; j < L; j++) {
        float e0 = __expf(o[2 * j]), e1 = __expf(o[2 * j + 1]);
        float r0 = __frcp_rn(1.f + e0);
        float r1 = __frcp_rn(1.f + e1);
        float py0 = yb[j] ? e0 * r0 : r0;
        float py1 = yb[j] ? r1 : e1 * r1;

        float m00 = t00 * py0, m01 = t01 * py1;
        float m10 = t10 * py0, m11 = t11 * py1;
        float n00 = m00 * A00 + m01 * A10;
        float n01 = m00 * A01 + m01 * A11;
        float n10 = m10 * A00 + m11 * A10;
        float n11 = m10 * A01 + m11 * A11;
        A00 = n00; A01 = n01; A10 = n10; A11 = n11;
    }
    // single end-of-segment power-of-2 normalization (8-step product can't underflow)
    float s = (A00 + A01) + (A10 + A11);
    int eb = (__float_as_int(s) >> 23) & 0xFF;
    float sc = __int_as_float((254 - eb) << 23);
    g_P4[g] = make_float4(A00 * sc, A01 * sc, A10 * sc, A11 * sc);
    g_E[g]  = eb - 127;
}

// ---------------- K2: boundary scan over segments (alpha & beta interleaved) ----------------
__global__ __launch_bounds__(256)
void k2_scan(const float* __restrict__ dyn)
{
    const int row = blockIdx.x * 256 + threadIdx.x;

    float d2 = dyn[row * 3 + 2];
    float ed2 = __expf(d2);
    float ri2 = __frcp_rn(1.f + ed2);
    float a0 = ri2, a1 = ed2 * ri2;
    int Ea = 0;
    float b0 = 1.f, b1 = 1.f;

#pragma unroll 4
    for (int k = 0; k < SEG; k++) {
        // ---- alpha chain (ascending) ----
        int gi = k * BN + row;
        float s  = a0 + a1;
        float rs = __frcp_rn(s);
        float C  = (float)Ea * LN2F + __logf(s);
        g_ab[gi] = make_float4(a0 * rs, a1 * rs, C, 0.f);

        float4 P = g_P4[gi];
        int Ek   = g_E[gi];
        float na0 = P.x * a0 + P.y * a1;
        float na1 = P.z * a0 + P.w * a1;
        float ss = na0 + na1;
        int eb = (__float_as_int(ss) >> 23) & 0xFF;
        float sca = __int_as_float((254 - eb) << 23);
        a0 = na0 * sca; a1 = na1 * sca;
        Ea += Ek + (eb - 127);

        // ---- beta chain (descending, independent) ----
        int kb  = SEG - 1 - k;
        int gib = kb * BN + row;
        g_bb[gib] = make_float2(b0, b1);
        if (kb > 0) {
            float4 Pb = g_P4[gib];
            float nb0 = Pb.x * b0 + Pb.z * b1;   // P^T * b
            float nb1 = Pb.y * b0 + Pb.w * b1;
            float sb = nb0 + nb1;
            int ebb = (__float_as_int(sb) >> 23) & 0xFF;
            float scb = __int_as_float((254 - ebb) << 23);
            b0 = nb0 * scb; b1 = nb1 * scb;
        }
    }
}

// ---------------- K3: per-segment outputs (normalized filter) ----------------
__global__ __launch_bounds__(128, 6)
void k3_outputs(const int* __restrict__ corr,
                const float* __restrict__ dyn,
                const float* __restrict__ obs,
                float* __restrict__ out)
{
    __shared__ float sA[128 * 17];
    __shared__ float sB[128 * 17];

    const int tid  = threadIdx.x;
    const int row0 = blockIdx.x * 128;
    const int row  = row0 + tid;
    const int seg  = blockIdx.y;

    float t00, t10, t01, t11;
    trans_from_dyn(dyn, row, t00, t10, t01, t11);

    float* outPred = out;
    float* outPost = out + (size_t)BN * TT * 2;
    float* outSm   = out + (size_t)2 * BN * TT * 2;

    float o[2 * L];
    const float4* op = (const float4*)(obs + ((size_t)row * TT + seg * L) * 2);
#pragma unroll
    for (int i = 0; i < 4; i++) {
        float4 v = op[i];
        o[4 * i + 0] = v.x; o[4 * i + 1] = v.y;
        o[4 * i + 2] = v.z; o[4 * i + 3] = v.w;
    }
    int yb[L];
    const int4* cp = (const int4*)(corr + (size_t)row * TT + seg * L);
#pragma unroll
    for (int i = 0; i < 2; i++) {
        int4 v = cp[i];
        yb[4 * i + 0] = v.x; yb[4 * i + 1] = v.y;
        yb[4 * i + 2] = v.z; yb[4 * i + 3] = v.w;
    }

    const int gi = seg * BN + row;
    float4 ab = g_ab[gi];
    float a0 = ab.x, a1 = ab.y, C = ab.z;

    float f0s[L], py0s[L], py1s[L];

    // ---- forward: pred + post + f0 ----
#pragma unroll
    for (int j = 0; j < L; j++) {
        int y = yb[j];
        float e0 = __expf(o[2 * j]), e1 = __expf(o[2 * j + 1]);
        float r0 = __frcp_rn(1.f + e0);
        float r1 = __frcp_rn(1.f + e1);
        float py0 = y ? e0 * r0 : r0;
        float py1 = y ? r1 : e1 * r1;
        py0s[j] = py0; py1s[j] = py1;

        float jj0 = a0 * py0;
        float jj1 = a1 * py1;
        float js  = jj0 + jj1;               // predictive prob of observed symbol
        float ljs = __logf(js);
        float lns = __logf(1.f - js);        // predictive probs sum to 1 (a normalized)
        float lp0 = y ? lns : ljs;
        float lp1 = y ? ljs : lns;
        float post0 = __logf(jj0) + C;
        float post1 = __logf(jj1) + C;

        float f = jj0 * __frcp_rn(js);
        f0s[j] = f;
        float fc = 1.f - f;
        a0 = t00 * f + t01 * fc;             // stays normalized (T columns sum to 1)
        a1 = t10 * f + t11 * fc;
        C += ljs;

        sA[tid * 17 + 2 * j]     = lp0;
        sA[tid * 17 + 2 * j + 1] = lp1;
        sB[tid * 17 + 2 * j]     = post0;
        sB[tid * 17 + 2 * j + 1] = post1;
    }
    __syncthreads();
#pragma unroll
    for (int i = 0; i < 16; i++) {
        int idx = i * 128 + tid;
        int r = idx >> 4, p = idx & 15;
        size_t g = (size_t)(row0 + r) * (TT * 2) + (size_t)seg * (L * 2) + p;
        outPred[g] = sA[r * 17 + p];
        outPost[g] = sB[r * 17 + p];
    }
    __syncthreads();

    // ---- backward: smoothed ----
    float2 bb = g_bb[gi];
    float b0 = bb.x, b1 = bb.y;

#pragma unroll
    for (int j = L - 1; j >= 0; j--) {
        float f = f0s[j];
        float g0 = f * b0;
        float g1 = (1.f - f) * b1;
        float rs = __frcp_rn(g0 + g1);
        sA[tid * 17 + 2 * j]     = __logf(g0 * rs);
        sA[tid * 17 + 2 * j + 1] = __logf(g1 * rs);

        float u0 = py0s[j] * b0;
        float u1 = py1s[j] * b1;
        float nb0 = t00 * u0 + t10 * u1;
        float nb1 = t01 * u0 + t11 * u1;
        float ss = nb0 + nb1;
        int eb = (__float_as_int(ss) >> 23) & 0xFF;
        float sc = __int_as_float((254 - eb) << 23);
        b0 = nb0 * sc; b1 = nb1 * sc;
    }
    __syncthreads();
#pragma unroll
    for (int i = 0; i < 16; i++) {
        int idx = i * 128 + tid;
        int r = idx >> 4, p = idx & 15;
        size_t g = (size_t)(row0 + r) * (TT * 2) + (size_t)seg * (L * 2) + p;
        outSm[g] = sA[r * 17 + p];
    }
}

extern "C" void kernel_launch(void* const* d_in, const int* in_sizes, int n_in,
                              void* d_out, int out_size)
{
    const int*   corr = (const int*)d_in[0];
    const float* dyn  = (const float*)d_in[1];
    const float* obs  = (const float*)d_in[2];
    float* out = (float*)d_out;

    k1_products<<<(BN * SEG) / 256, 256>>>(corr, dyn, obs);
    k2_scan<<<BN / 256, 256>>>(dyn);
    dim3 g3(BN / 128, SEG);
    k3_outputs<<<g3, 128>>>(corr, dyn, obs, out);
}